// round 5
// baseline (speedup 1.0000x reference)
#include <cuda_runtime.h>
#include <math.h>

#define BB 4
#define TT 4096
#define EE 256
#define AA 64
#define MTOT (BB*TT)   // 16384

// Scratch for projected q/k/v (device globals: no allocation allowed)
__device__ float g_q[BB*TT*AA];
__device__ float g_k[BB*TT*AA];
__device__ float g_v[BB*TT*AA];

// ---------------------------------------------------------------------------
// Projection: C[m, a] = X[m, :] @ W[:, a] + b[a]   (scale folded into Q)
// grid = (MTOT/64, 3), block = 256 threads, 64x64 tiles, 4x4 register tiles.
// ---------------------------------------------------------------------------
__global__ __launch_bounds__(256) void proj_kernel(
    const float* __restrict__ X,
    const float* __restrict__ Wk, const float* __restrict__ bk,
    const float* __restrict__ Wq, const float* __restrict__ bq,
    const float* __restrict__ Wv, const float* __restrict__ bv)
{
    __shared__ float Xs[64][68];  // transposed: Xs[e][i], pad for f4 alignment
    __shared__ float Ws[64][68];  // Ws[e][n]

    const float* W; const float* bias; float* outp; float scl;
    if (blockIdx.y == 0)      { W = Wq; bias = bq; outp = g_q; scl = 0.125f; }
    else if (blockIdx.y == 1) { W = Wk; bias = bk; outp = g_k; scl = 1.0f; }
    else                      { W = Wv; bias = bv; outp = g_v; scl = 1.0f; }

    const int t  = threadIdx.x;
    const int tx = t & 15;
    const int ty = t >> 4;
    const int m0 = blockIdx.x * 64;

    float acc[4][4];
#pragma unroll
    for (int r = 0; r < 4; r++)
#pragma unroll
        for (int c = 0; c < 4; c++) acc[r][c] = 0.f;

    for (int e0 = 0; e0 < EE; e0 += 64) {
#pragma unroll
        for (int rep = 0; rep < 16; rep++) {
            int idx = t + rep * 256;
            int i = idx >> 6;
            int j = idx & 63;
            Xs[j][i] = X[(m0 + i) * EE + e0 + j];   // transpose on store
            Ws[i][j] = W[(e0 + i) * AA + j];
        }
        __syncthreads();
#pragma unroll 8
        for (int e = 0; e < 64; e++) {
            float4 xa = *(const float4*)&Xs[e][ty * 4];
            float4 wb = *(const float4*)&Ws[e][tx * 4];
            acc[0][0] += xa.x * wb.x; acc[0][1] += xa.x * wb.y; acc[0][2] += xa.x * wb.z; acc[0][3] += xa.x * wb.w;
            acc[1][0] += xa.y * wb.x; acc[1][1] += xa.y * wb.y; acc[1][2] += xa.y * wb.z; acc[1][3] += xa.y * wb.w;
            acc[2][0] += xa.z * wb.x; acc[2][1] += xa.z * wb.y; acc[2][2] += xa.z * wb.z; acc[2][3] += xa.z * wb.w;
            acc[3][0] += xa.w * wb.x; acc[3][1] += xa.w * wb.y; acc[3][2] += xa.w * wb.z; acc[3][3] += xa.w * wb.w;
        }
        __syncthreads();
    }

#pragma unroll
    for (int r = 0; r < 4; r++) {
#pragma unroll
        for (int c = 0; c < 4; c++) {
            int n = tx * 4 + c;
            outp[(m0 + ty * 4 + r) * AA + n] = (acc[r][c] + bias[n]) * scl;
        }
    }
}

// ---------------------------------------------------------------------------
// Flash attention (causal), fp32, BQ = BK = 64, D = 64.
// grid = (TT/64, BB), block = 256 threads.
// ---------------------------------------------------------------------------
__global__ __launch_bounds__(256) void flash_kernel(float* __restrict__ out)
{
    extern __shared__ float sm[];
    float* Qt   = sm;               // [64][68] d-major: Qt[d][i]
    float* Kt   = Qt + 64 * 68;     // [64][68] d-major: Kt[d][j]
    float* Vs   = Kt + 64 * 68;     // [64][68] row-major: Vs[j][d]
    float* Ss   = Vs + 64 * 68;     // [64][68] scores / probs
    float* rowm = Ss + 64 * 68;     // [64]
    float* rowl = rowm + 64;        // [64]
    float* rowc = rowl + 64;        // [64]

    const int t  = threadIdx.x;
    const int tx = t & 15;
    const int ty = t >> 4;
    const int qt = blockIdx.x;
    const int b  = blockIdx.y;

    const float* qp    = g_q + (b * TT + qt * 64) * AA;
    const float* kbase = g_k + b * TT * AA;
    const float* vbase = g_v + b * TT * AA;

#pragma unroll
    for (int rep = 0; rep < 16; rep++) {
        int idx = t + rep * 256;
        int i = idx >> 6;
        int a = idx & 63;
        Qt[a * 68 + i] = qp[i * AA + a];
    }
    if (t < 64) { rowm[t] = -INFINITY; rowl[t] = 0.f; }

    float O[4][4];
#pragma unroll
    for (int r = 0; r < 4; r++)
#pragma unroll
        for (int c = 0; c < 4; c++) O[r][c] = 0.f;

    __syncthreads();

    for (int kt = 0; kt <= qt; kt++) {
        const float* kp = kbase + kt * 64 * AA;
        const float* vp = vbase + kt * 64 * AA;
#pragma unroll
        for (int rep = 0; rep < 16; rep++) {
            int idx = t + rep * 256;
            int i = idx >> 6;
            int a = idx & 63;
            Kt[a * 68 + i] = kp[i * AA + a];
            Vs[i * 68 + a] = vp[i * AA + a];
        }
        __syncthreads();

        // ---- S = Q @ K^T (scale already folded into Q) ----
        float s[4][4];
#pragma unroll
        for (int r = 0; r < 4; r++)
#pragma unroll
            for (int c = 0; c < 4; c++) s[r][c] = 0.f;

#pragma unroll 8
        for (int d = 0; d < 64; d++) {
            float4 qa = *(const float4*)&Qt[d * 68 + ty * 4];
            float4 kb = *(const float4*)&Kt[d * 68 + tx * 4];
            s[0][0] += qa.x * kb.x; s[0][1] += qa.x * kb.y; s[0][2] += qa.x * kb.z; s[0][3] += qa.x * kb.w;
            s[1][0] += qa.y * kb.x; s[1][1] += qa.y * kb.y; s[1][2] += qa.y * kb.z; s[1][3] += qa.y * kb.w;
            s[2][0] += qa.z * kb.x; s[2][1] += qa.z * kb.y; s[2][2] += qa.z * kb.z; s[2][3] += qa.z * kb.w;
            s[3][0] += qa.w * kb.x; s[3][1] += qa.w * kb.y; s[3][2] += qa.w * kb.z; s[3][3] += qa.w * kb.w;
        }

        // Causal mask (only needed on the diagonal tile; tiles are aligned)
        if (kt == qt) {
#pragma unroll
            for (int r = 0; r < 4; r++)
#pragma unroll
                for (int c = 0; c < 4; c++)
                    if (tx * 4 + c > ty * 4 + r) s[r][c] = -INFINITY;
        }

#pragma unroll
        for (int r = 0; r < 4; r++)
#pragma unroll
            for (int c = 0; c < 4; c++)
                Ss[(ty * 4 + r) * 68 + tx * 4 + c] = s[r][c];
        __syncthreads();

        // ---- online softmax row pass: one thread per q row ----
        if (t < 64) {
            float* srow = Ss + t * 68;
            float mo = rowm[t];
            float mx = mo;
#pragma unroll 8
            for (int j = 0; j < 64; j++) mx = fmaxf(mx, srow[j]);
            float corr = __expf(mo - mx);   // mo=-inf -> 0 (mx finite: diag always valid)
            float sum = 0.f;
#pragma unroll 8
            for (int j = 0; j < 64; j++) {
                float p = __expf(srow[j] - mx);
                srow[j] = p;
                sum += p;
            }
            rowl[t] = rowl[t] * corr + sum;
            rowm[t] = mx;
            rowc[t] = corr;
        }
        __syncthreads();

        // ---- O = O * corr + P @ V ----
        float cr[4];
#pragma unroll
        for (int r = 0; r < 4; r++) cr[r] = rowc[ty * 4 + r];
#pragma unroll
        for (int r = 0; r < 4; r++)
#pragma unroll
            for (int c = 0; c < 4; c++) O[r][c] *= cr[r];

#pragma unroll 8
        for (int j = 0; j < 64; j++) {
            float4 vb = *(const float4*)&Vs[j * 68 + tx * 4];
            float p0 = Ss[(ty * 4 + 0) * 68 + j];
            float p1 = Ss[(ty * 4 + 1) * 68 + j];
            float p2 = Ss[(ty * 4 + 2) * 68 + j];
            float p3 = Ss[(ty * 4 + 3) * 68 + j];
            O[0][0] += p0 * vb.x; O[0][1] += p0 * vb.y; O[0][2] += p0 * vb.z; O[0][3] += p0 * vb.w;
            O[1][0] += p1 * vb.x; O[1][1] += p1 * vb.y; O[1][2] += p1 * vb.z; O[1][3] += p1 * vb.w;
            O[2][0] += p2 * vb.x; O[2][1] += p2 * vb.y; O[2][2] += p2 * vb.z; O[2][3] += p2 * vb.w;
            O[3][0] += p3 * vb.x; O[3][1] += p3 * vb.y; O[3][2] += p3 * vb.z; O[3][3] += p3 * vb.w;
        }
        __syncthreads();
    }

    // ---- epilogue: divide by l ----
    float inv[4];
#pragma unroll
    for (int r = 0; r < 4; r++) inv[r] = 1.0f / rowl[ty * 4 + r];

#pragma unroll
    for (int r = 0; r < 4; r++) {
#pragma unroll
        for (int c = 0; c < 4; c++) {
            out[(b * TT + qt * 64 + ty * 4 + r) * AA + tx * 4 + c] = O[r][c] * inv[r];
        }
    }
}

static const int FLASH_SMEM = (4 * 64 * 68 + 3 * 64) * (int)sizeof(float);  // 70400

extern "C" void kernel_launch(void* const* d_in, const int* in_sizes, int n_in,
                              void* d_out, int out_size)
{
    const float* X  = (const float*)d_in[0];
    const float* Wk = (const float*)d_in[1];
    const float* bk = (const float*)d_in[2];
    const float* Wq = (const float*)d_in[3];
    const float* bq = (const float*)d_in[4];
    const float* Wv = (const float*)d_in[5];
    const float* bv = (const float*)d_in[6];
    float* out = (float*)d_out;

    cudaFuncSetAttribute(flash_kernel, cudaFuncAttributeMaxDynamicSharedMemorySize, FLASH_SMEM);

    dim3 pg(MTOT / 64, 3);
    proj_kernel<<<pg, 256>>>(X, Wk, bk, Wq, bq, Wv, bv);

    dim3 fg(TT / 64, BB);
    flash_kernel<<<fg, 256, FLASH_SMEM>>>(out);
}

// round 6
// speedup vs baseline: 1.0008x; 1.0008x over previous
#include <cuda_runtime.h>
#include <math.h>

#define BB 4
#define TT 4096
#define EE 256
#define AA 64
#define MTOT (BB*TT)   // 16384

// Scratch for projected q/k/v (device globals: no allocation allowed)
__device__ float g_q[BB*TT*AA];
__device__ float g_k[BB*TT*AA];
__device__ float g_v[BB*TT*AA];

// ---------------------------------------------------------------------------
// Projection: C[m, a] = X[m, :] @ W[:, a] + b[a]   (scale folded into Q)
// grid = (MTOT/64, 3), block = 256 threads, 64x64 tiles, 4x4 register tiles.
// ---------------------------------------------------------------------------
__global__ __launch_bounds__(256) void proj_kernel(
    const float* __restrict__ X,
    const float* __restrict__ Wk, const float* __restrict__ bk,
    const float* __restrict__ Wq, const float* __restrict__ bq,
    const float* __restrict__ Wv, const float* __restrict__ bv)
{
    __shared__ float Xs[64][68];  // transposed: Xs[e][i], pad for f4 alignment
    __shared__ float Ws[64][68];  // Ws[e][n]

    const float* W; const float* bias; float* outp; float scl;
    if (blockIdx.y == 0)      { W = Wq; bias = bq; outp = g_q; scl = 0.125f; }
    else if (blockIdx.y == 1) { W = Wk; bias = bk; outp = g_k; scl = 1.0f; }
    else                      { W = Wv; bias = bv; outp = g_v; scl = 1.0f; }

    const int t  = threadIdx.x;
    const int tx = t & 15;
    const int ty = t >> 4;
    const int m0 = blockIdx.x * 64;

    float acc[4][4];
#pragma unroll
    for (int r = 0; r < 4; r++)
#pragma unroll
        for (int c = 0; c < 4; c++) acc[r][c] = 0.f;

    for (int e0 = 0; e0 < EE; e0 += 64) {
#pragma unroll
        for (int rep = 0; rep < 16; rep++) {
            int idx = t + rep * 256;
            int i = idx >> 6;
            int j = idx & 63;
            Xs[j][i] = X[(m0 + i) * EE + e0 + j];   // transpose on store
            Ws[i][j] = W[(e0 + i) * AA + j];
        }
        __syncthreads();
#pragma unroll 8
        for (int e = 0; e < 64; e++) {
            float4 xa = *(const float4*)&Xs[e][ty * 4];
            float4 wb = *(const float4*)&Ws[e][tx * 4];
            acc[0][0] += xa.x * wb.x; acc[0][1] += xa.x * wb.y; acc[0][2] += xa.x * wb.z; acc[0][3] += xa.x * wb.w;
            acc[1][0] += xa.y * wb.x; acc[1][1] += xa.y * wb.y; acc[1][2] += xa.y * wb.z; acc[1][3] += xa.y * wb.w;
            acc[2][0] += xa.z * wb.x; acc[2][1] += xa.z * wb.y; acc[2][2] += xa.z * wb.z; acc[2][3] += xa.z * wb.w;
            acc[3][0] += xa.w * wb.x; acc[3][1] += xa.w * wb.y; acc[3][2] += xa.w * wb.z; acc[3][3] += xa.w * wb.w;
        }
        __syncthreads();
    }

#pragma unroll
    for (int r = 0; r < 4; r++) {
#pragma unroll
        for (int c = 0; c < 4; c++) {
            int n = tx * 4 + c;
            outp[(m0 + ty * 4 + r) * AA + n] = (acc[r][c] + bias[n]) * scl;
        }
    }
}

// ---------------------------------------------------------------------------
// Flash attention (causal), fp32, BQ = BK = 64, D = 64.
// grid = (TT/64, BB), block = 256 threads.
// ---------------------------------------------------------------------------
__global__ __launch_bounds__(256) void flash_kernel(float* __restrict__ out)
{
    extern __shared__ float sm[];
    float* Qt   = sm;               // [64][68] d-major: Qt[d][i]
    float* Kt   = Qt + 64 * 68;     // [64][68] d-major: Kt[d][j]
    float* Vs   = Kt + 64 * 68;     // [64][68] row-major: Vs[j][d]
    float* Ss   = Vs + 64 * 68;     // [64][68] scores / probs
    float* rowm = Ss + 64 * 68;     // [64]
    float* rowl = rowm + 64;        // [64]
    float* rowc = rowl + 64;        // [64]

    const int t  = threadIdx.x;
    const int tx = t & 15;
    const int ty = t >> 4;
    const int qt = blockIdx.x;
    const int b  = blockIdx.y;

    const float* qp    = g_q + (b * TT + qt * 64) * AA;
    const float* kbase = g_k + b * TT * AA;
    const float* vbase = g_v + b * TT * AA;

#pragma unroll
    for (int rep = 0; rep < 16; rep++) {
        int idx = t + rep * 256;
        int i = idx >> 6;
        int a = idx & 63;
        Qt[a * 68 + i] = qp[i * AA + a];
    }
    if (t < 64) { rowm[t] = -INFINITY; rowl[t] = 0.f; }

    float O[4][4];
#pragma unroll
    for (int r = 0; r < 4; r++)
#pragma unroll
        for (int c = 0; c < 4; c++) O[r][c] = 0.f;

    __syncthreads();

    for (int kt = 0; kt <= qt; kt++) {
        const float* kp = kbase + kt * 64 * AA;
        const float* vp = vbase + kt * 64 * AA;
#pragma unroll
        for (int rep = 0; rep < 16; rep++) {
            int idx = t + rep * 256;
            int i = idx >> 6;
            int a = idx & 63;
            Kt[a * 68 + i] = kp[i * AA + a];
            Vs[i * 68 + a] = vp[i * AA + a];
        }
        __syncthreads();

        // ---- S = Q @ K^T (scale already folded into Q) ----
        float s[4][4];
#pragma unroll
        for (int r = 0; r < 4; r++)
#pragma unroll
            for (int c = 0; c < 4; c++) s[r][c] = 0.f;

#pragma unroll 8
        for (int d = 0; d < 64; d++) {
            float4 qa = *(const float4*)&Qt[d * 68 + ty * 4];
            float4 kb = *(const float4*)&Kt[d * 68 + tx * 4];
            s[0][0] += qa.x * kb.x; s[0][1] += qa.x * kb.y; s[0][2] += qa.x * kb.z; s[0][3] += qa.x * kb.w;
            s[1][0] += qa.y * kb.x; s[1][1] += qa.y * kb.y; s[1][2] += qa.y * kb.z; s[1][3] += qa.y * kb.w;
            s[2][0] += qa.z * kb.x; s[2][1] += qa.z * kb.y; s[2][2] += qa.z * kb.z; s[2][3] += qa.z * kb.w;
            s[3][0] += qa.w * kb.x; s[3][1] += qa.w * kb.y; s[3][2] += qa.w * kb.z; s[3][3] += qa.w * kb.w;
        }

        // Causal mask (only needed on the diagonal tile; tiles are aligned)
        if (kt == qt) {
#pragma unroll
            for (int r = 0; r < 4; r++)
#pragma unroll
                for (int c = 0; c < 4; c++)
                    if (tx * 4 + c > ty * 4 + r) s[r][c] = -INFINITY;
        }

#pragma unroll
        for (int r = 0; r < 4; r++)
#pragma unroll
            for (int c = 0; c < 4; c++)
                Ss[(ty * 4 + r) * 68 + tx * 4 + c] = s[r][c];
        __syncthreads();

        // ---- online softmax row pass: one thread per q row ----
        if (t < 64) {
            float* srow = Ss + t * 68;
            float mo = rowm[t];
            float mx = mo;
#pragma unroll 8
            for (int j = 0; j < 64; j++) mx = fmaxf(mx, srow[j]);
            float corr = __expf(mo - mx);   // mo=-inf -> 0 (mx finite: diag always valid)
            float sum = 0.f;
#pragma unroll 8
            for (int j = 0; j < 64; j++) {
                float p = __expf(srow[j] - mx);
                srow[j] = p;
                sum += p;
            }
            rowl[t] = rowl[t] * corr + sum;
            rowm[t] = mx;
            rowc[t] = corr;
        }
        __syncthreads();

        // ---- O = O * corr + P @ V ----
        float cr[4];
#pragma unroll
        for (int r = 0; r < 4; r++) cr[r] = rowc[ty * 4 + r];
#pragma unroll
        for (int r = 0; r < 4; r++)
#pragma unroll
            for (int c = 0; c < 4; c++) O[r][c] *= cr[r];

#pragma unroll 8
        for (int j = 0; j < 64; j++) {
            float4 vb = *(const float4*)&Vs[j * 68 + tx * 4];
            float p0 = Ss[(ty * 4 + 0) * 68 + j];
            float p1 = Ss[(ty * 4 + 1) * 68 + j];
            float p2 = Ss[(ty * 4 + 2) * 68 + j];
            float p3 = Ss[(ty * 4 + 3) * 68 + j];
            O[0][0] += p0 * vb.x; O[0][1] += p0 * vb.y; O[0][2] += p0 * vb.z; O[0][3] += p0 * vb.w;
            O[1][0] += p1 * vb.x; O[1][1] += p1 * vb.y; O[1][2] += p1 * vb.z; O[1][3] += p1 * vb.w;
            O[2][0] += p2 * vb.x; O[2][1] += p2 * vb.y; O[2][2] += p2 * vb.z; O[2][3] += p2 * vb.w;
            O[3][0] += p3 * vb.x; O[3][1] += p3 * vb.y; O[3][2] += p3 * vb.z; O[3][3] += p3 * vb.w;
        }
        __syncthreads();
    }

    // ---- epilogue: divide by l ----
    float inv[4];
#pragma unroll
    for (int r = 0; r < 4; r++) inv[r] = 1.0f / rowl[ty * 4 + r];

#pragma unroll
    for (int r = 0; r < 4; r++) {
#pragma unroll
        for (int c = 0; c < 4; c++) {
            out[(b * TT + qt * 64 + ty * 4 + r) * AA + tx * 4 + c] = O[r][c] * inv[r];
        }
    }
}

static const int FLASH_SMEM = (4 * 64 * 68 + 3 * 64) * (int)sizeof(float);  // 70400

extern "C" void kernel_launch(void* const* d_in, const int* in_sizes, int n_in,
                              void* d_out, int out_size)
{
    const float* X  = (const float*)d_in[0];
    const float* Wk = (const float*)d_in[1];
    const float* bk = (const float*)d_in[2];
    const float* Wq = (const float*)d_in[3];
    const float* bq = (const float*)d_in[4];
    const float* Wv = (const float*)d_in[5];
    const float* bv = (const float*)d_in[6];
    float* out = (float*)d_out;

    cudaFuncSetAttribute(flash_kernel, cudaFuncAttributeMaxDynamicSharedMemorySize, FLASH_SMEM);

    dim3 pg(MTOT / 64, 3);
    proj_kernel<<<pg, 256>>>(X, Wk, bk, Wq, bq, Wv, bv);

    dim3 fg(TT / 64, BB);
    flash_kernel<<<fg, 256, FLASH_SMEM>>>(out);
}

// round 7
// speedup vs baseline: 1.5526x; 1.5514x over previous
#include <cuda_runtime.h>
#include <math.h>

#define BB 4
#define TT 4096
#define EE 256
#define AA 64
#define MTOT (BB*TT)   // 16384

__device__ float g_q[BB*TT*AA];
__device__ float g_k[BB*TT*AA];
__device__ float g_v[BB*TT*AA];

// ---- packed f32x2 helpers (PTX-only on sm_103a) ----
typedef unsigned long long ull_t;

__device__ __forceinline__ ull_t pack2(float x) {
    ull_t r;
    asm("mov.b64 %0, {%1, %1};" : "=l"(r) : "f"(x));
    return r;
}
__device__ __forceinline__ void fma2(ull_t& acc, ull_t a, ull_t b) {
    asm("fma.rn.f32x2 %0, %1, %2, %0;" : "+l"(acc) : "l"(a), "l"(b));
}
__device__ __forceinline__ ull_t mul2(ull_t a, ull_t b) {
    ull_t r;
    asm("mul.rn.f32x2 %0, %1, %2;" : "=l"(r) : "l"(a), "l"(b));
    return r;
}
__device__ __forceinline__ void unpack2(ull_t v, float& lo, float& hi) {
    asm("mov.b64 {%0, %1}, %2;" : "=f"(lo), "=f"(hi) : "l"(v));
}

// ---------------------------------------------------------------------------
// Projection: C[m, a] = X[m, :] @ W[:, a] + b[a]   (scale folded into Q)
// ---------------------------------------------------------------------------
__global__ __launch_bounds__(256) void proj_kernel(
    const float* __restrict__ X,
    const float* __restrict__ Wk, const float* __restrict__ bk,
    const float* __restrict__ Wq, const float* __restrict__ bq,
    const float* __restrict__ Wv, const float* __restrict__ bv)
{
    __shared__ float Xs[64][68];
    __shared__ float Ws[64][68];

    const float* W; const float* bias; float* outp; float scl;
    if (blockIdx.y == 0)      { W = Wq; bias = bq; outp = g_q; scl = 0.125f; }
    else if (blockIdx.y == 1) { W = Wk; bias = bk; outp = g_k; scl = 1.0f; }
    else                      { W = Wv; bias = bv; outp = g_v; scl = 1.0f; }

    const int t  = threadIdx.x;
    const int tx = t & 15;
    const int ty = t >> 4;
    const int m0 = blockIdx.x * 64;

    float acc[4][4];
#pragma unroll
    for (int r = 0; r < 4; r++)
#pragma unroll
        for (int c = 0; c < 4; c++) acc[r][c] = 0.f;

    for (int e0 = 0; e0 < EE; e0 += 64) {
#pragma unroll
        for (int rep = 0; rep < 16; rep++) {
            int idx = t + rep * 256;
            int i = idx >> 6;
            int j = idx & 63;
            Xs[j][i] = X[(m0 + i) * EE + e0 + j];
            Ws[i][j] = W[(e0 + i) * AA + j];
        }
        __syncthreads();
#pragma unroll 8
        for (int e = 0; e < 64; e++) {
            float4 xa = *(const float4*)&Xs[e][ty * 4];
            float4 wb = *(const float4*)&Ws[e][tx * 4];
            acc[0][0] += xa.x * wb.x; acc[0][1] += xa.x * wb.y; acc[0][2] += xa.x * wb.z; acc[0][3] += xa.x * wb.w;
            acc[1][0] += xa.y * wb.x; acc[1][1] += xa.y * wb.y; acc[1][2] += xa.y * wb.z; acc[1][3] += xa.y * wb.w;
            acc[2][0] += xa.z * wb.x; acc[2][1] += xa.z * wb.y; acc[2][2] += xa.z * wb.z; acc[2][3] += xa.z * wb.w;
            acc[3][0] += xa.w * wb.x; acc[3][1] += xa.w * wb.y; acc[3][2] += xa.w * wb.z; acc[3][3] += xa.w * wb.w;
        }
        __syncthreads();
    }

#pragma unroll
    for (int r = 0; r < 4; r++) {
#pragma unroll
        for (int c = 0; c < 4; c++) {
            int n = tx * 4 + c;
            outp[(m0 + ty * 4 + r) * AA + n] = (acc[r][c] + bias[n]) * scl;
        }
    }
}

// ---------------------------------------------------------------------------
// Flash attention (causal), fp32 with f32x2 packed FMA.
// grid = (32, BB): CTA x handles q-tiles x and 63-x (perfect causal balance).
// block = 256 threads; BQ = BK = 64, D = 64.
// ---------------------------------------------------------------------------
__global__ __launch_bounds__(256, 2) void flash_kernel(float* __restrict__ out)
{
    extern __shared__ float sm[];
    float* Qt = sm;               // [64 d][68]  d-major: Qt[d][i]
    float* Kt = Qt + 64 * 68;     // [64 d][68]  d-major: Kt[d][j]
    float* Vs = Kt + 64 * 68;     // [64 j][68]  row-major: Vs[j][d]
    float* Pt = Vs + 64 * 68;     // [64 j][68]  TRANSPOSED probs: Pt[j][i]

    const int t  = threadIdx.x;
    const int tx = t & 15;
    const int ty = t >> 4;
    const int b  = blockIdx.y;

#pragma unroll 1
    for (int half = 0; half < 2; half++) {
        const int qt = (half == 0) ? blockIdx.x : 63 - blockIdx.x;

        const float* qp    = g_q + (b * TT + qt * 64) * AA;
        const float* kbase = g_k + b * TT * AA;
        const float* vbase = g_v + b * TT * AA;

        // load Q tile (transposed).  Covered by the first barrier in the loop.
#pragma unroll
        for (int rep = 0; rep < 16; rep++) {
            int idx = t + rep * 256;
            int i = idx >> 6;
            int a = idx & 63;
            Qt[a * 68 + i] = qp[i * AA + a];
        }

        float m_run[4], l_run[4];
        ull_t O2[4][2];
#pragma unroll
        for (int r = 0; r < 4; r++) {
            m_run[r] = -INFINITY; l_run[r] = 0.f;
            O2[r][0] = 0ULL; O2[r][1] = 0ULL;
        }

#pragma unroll 1
        for (int kt = 0; kt <= qt; kt++) {
            const float* kp = kbase + kt * 64 * AA;
            const float* vp = vbase + kt * 64 * AA;
#pragma unroll
            for (int rep = 0; rep < 16; rep++) {
                int idx = t + rep * 256;
                int i = idx >> 6;
                int a = idx & 63;
                Kt[a * 68 + i] = kp[i * AA + a];
                Vs[i * 68 + a] = vp[i * AA + a];
            }
            __syncthreads();   // A: K/V (and Q on first iter) visible

            // ---- S = Q @ K^T, packed f32x2 ----
            ull_t s2[4][2];
#pragma unroll
            for (int r = 0; r < 4; r++) { s2[r][0] = 0ULL; s2[r][1] = 0ULL; }

#pragma unroll 4
            for (int d = 0; d < 64; d++) {
                float4 qa = *(const float4*)&Qt[d * 68 + ty * 4];
                ulonglong2 kb = *(const ulonglong2*)&Kt[d * 68 + tx * 4];
                ull_t q0 = pack2(qa.x), q1 = pack2(qa.y), q2 = pack2(qa.z), q3 = pack2(qa.w);
                fma2(s2[0][0], q0, kb.x); fma2(s2[0][1], q0, kb.y);
                fma2(s2[1][0], q1, kb.x); fma2(s2[1][1], q1, kb.y);
                fma2(s2[2][0], q2, kb.x); fma2(s2[2][1], q2, kb.y);
                fma2(s2[3][0], q3, kb.x); fma2(s2[3][1], q3, kb.y);
            }

            float s[4][4];
#pragma unroll
            for (int r = 0; r < 4; r++) {
                unpack2(s2[r][0], s[r][0], s[r][1]);
                unpack2(s2[r][1], s[r][2], s[r][3]);
            }

            if (kt == qt) {
#pragma unroll
                for (int r = 0; r < 4; r++)
#pragma unroll
                    for (int c = 0; c < 4; c++)
                        if (tx * 4 + c > ty * 4 + r) s[r][c] = -INFINITY;
            }

            // ---- register softmax: reduce over the 16-lane tx group ----
            float rm[4];
#pragma unroll
            for (int r = 0; r < 4; r++)
                rm[r] = fmaxf(fmaxf(s[r][0], s[r][1]), fmaxf(s[r][2], s[r][3]));
#pragma unroll
            for (int off = 1; off < 16; off <<= 1) {
#pragma unroll
                for (int r = 0; r < 4; r++)
                    rm[r] = fmaxf(rm[r], __shfl_xor_sync(0xffffffffu, rm[r], off));
            }

            float corr[4];
#pragma unroll
            for (int r = 0; r < 4; r++) {
                float mnew = fmaxf(m_run[r], rm[r]);
                corr[r] = __expf(m_run[r] - mnew);   // m_run=-inf -> 0
                m_run[r] = mnew;
            }

            float rs[4];
#pragma unroll
            for (int r = 0; r < 4; r++) {
#pragma unroll
                for (int c = 0; c < 4; c++)
                    s[r][c] = __expf(s[r][c] - m_run[r]);
                rs[r] = (s[r][0] + s[r][1]) + (s[r][2] + s[r][3]);
            }
#pragma unroll
            for (int off = 1; off < 16; off <<= 1) {
#pragma unroll
                for (int r = 0; r < 4; r++)
                    rs[r] += __shfl_xor_sync(0xffffffffu, rs[r], off);
            }
#pragma unroll
            for (int r = 0; r < 4; r++)
                l_run[r] = l_run[r] * corr[r] + rs[r];

            // ---- write probs TRANSPOSED: Pt[col][row], float4 along rows ----
#pragma unroll
            for (int c = 0; c < 4; c++) {
                float4 pv = make_float4(s[0][c], s[1][c], s[2][c], s[3][c]);
                *(float4*)&Pt[(tx * 4 + c) * 68 + ty * 4] = pv;
            }
            __syncthreads();   // B: Pt visible

            // ---- O = O * corr + P @ V, packed f32x2 ----
#pragma unroll
            for (int r = 0; r < 4; r++) {
                ull_t cp = pack2(corr[r]);
                O2[r][0] = mul2(O2[r][0], cp);
                O2[r][1] = mul2(O2[r][1], cp);
            }

#pragma unroll 4
            for (int j = 0; j < 64; j++) {
                float4 pa = *(const float4*)&Pt[j * 68 + ty * 4];     // broadcast
                ulonglong2 vb = *(const ulonglong2*)&Vs[j * 68 + tx * 4];
                ull_t p0 = pack2(pa.x), p1 = pack2(pa.y), p2 = pack2(pa.z), p3 = pack2(pa.w);
                fma2(O2[0][0], p0, vb.x); fma2(O2[0][1], p0, vb.y);
                fma2(O2[1][0], p1, vb.x); fma2(O2[1][1], p1, vb.y);
                fma2(O2[2][0], p2, vb.x); fma2(O2[2][1], p2, vb.y);
                fma2(O2[3][0], p3, vb.x); fma2(O2[3][1], p3, vb.y);
            }
            __syncthreads();   // C: PV done, buffers free
        }

        // ---- epilogue ----
#pragma unroll
        for (int r = 0; r < 4; r++) {
            float inv = 1.0f / l_run[r];
            float o0, o1, o2, o3;
            unpack2(O2[r][0], o0, o1);
            unpack2(O2[r][1], o2, o3);
            float4 ov = make_float4(o0 * inv, o1 * inv, o2 * inv, o3 * inv);
            *(float4*)&out[(b * TT + qt * 64 + ty * 4 + r) * AA + tx * 4] = ov;
        }
        __syncthreads();   // Qt reuse safety for next half
    }
}

static const int FLASH_SMEM = 4 * 64 * 68 * (int)sizeof(float);  // 69632

extern "C" void kernel_launch(void* const* d_in, const int* in_sizes, int n_in,
                              void* d_out, int out_size)
{
    const float* X  = (const float*)d_in[0];
    const float* Wk = (const float*)d_in[1];
    const float* bk = (const float*)d_in[2];
    const float* Wq = (const float*)d_in[3];
    const float* bq = (const float*)d_in[4];
    const float* Wv = (const float*)d_in[5];
    const float* bv = (const float*)d_in[6];
    float* out = (float*)d_out;

    cudaFuncSetAttribute(flash_kernel, cudaFuncAttributeMaxDynamicSharedMemorySize, FLASH_SMEM);

    dim3 pg(MTOT / 64, 3);
    proj_kernel<<<pg, 256>>>(X, Wk, bk, Wq, bq, Wv, bv);

    dim3 fg(32, BB);
    flash_kernel<<<fg, 256, FLASH_SMEM>>>(out);
}

// round 8
// speedup vs baseline: 1.5609x; 1.0053x over previous
#include <cuda_runtime.h>
#include <math.h>

#define BB 4
#define TT 4096
#define EE 256
#define AA 64
#define MTOT (BB*TT)   // 16384

__device__ float g_q[BB*TT*AA];
__device__ float g_k[BB*TT*AA];
__device__ float g_v[BB*TT*AA];

// ---- packed f32x2 helpers (PTX-only on sm_103a) ----
typedef unsigned long long ull_t;

__device__ __forceinline__ ull_t pack2(float x) {
    ull_t r;
    asm("mov.b64 %0, {%1, %1};" : "=l"(r) : "f"(x));
    return r;
}
__device__ __forceinline__ void fma2(ull_t& acc, ull_t a, ull_t b) {
    asm("fma.rn.f32x2 %0, %1, %2, %0;" : "+l"(acc) : "l"(a), "l"(b));
}
__device__ __forceinline__ ull_t mul2(ull_t a, ull_t b) {
    ull_t r;
    asm("mul.rn.f32x2 %0, %1, %2;" : "=l"(r) : "l"(a), "l"(b));
    return r;
}
__device__ __forceinline__ void unpack2(ull_t v, float& lo, float& hi) {
    asm("mov.b64 {%0, %1}, %2;" : "=f"(lo), "=f"(hi) : "l"(v));
}

// ---------------------------------------------------------------------------
// Projection: C[m, a] = X[m, :] @ W[:, a] + b[a]   (scale folded into Q)
// ---------------------------------------------------------------------------
__global__ __launch_bounds__(256) void proj_kernel(
    const float* __restrict__ X,
    const float* __restrict__ Wk, const float* __restrict__ bk,
    const float* __restrict__ Wq, const float* __restrict__ bq,
    const float* __restrict__ Wv, const float* __restrict__ bv)
{
    __shared__ float Xs[64][68];
    __shared__ float Ws[64][68];

    const float* W; const float* bias; float* outp; float scl;
    if (blockIdx.y == 0)      { W = Wq; bias = bq; outp = g_q; scl = 0.125f; }
    else if (blockIdx.y == 1) { W = Wk; bias = bk; outp = g_k; scl = 1.0f; }
    else                      { W = Wv; bias = bv; outp = g_v; scl = 1.0f; }

    const int t  = threadIdx.x;
    const int tx = t & 15;
    const int ty = t >> 4;
    const int m0 = blockIdx.x * 64;

    float acc[4][4];
#pragma unroll
    for (int r = 0; r < 4; r++)
#pragma unroll
        for (int c = 0; c < 4; c++) acc[r][c] = 0.f;

    for (int e0 = 0; e0 < EE; e0 += 64) {
#pragma unroll
        for (int rep = 0; rep < 16; rep++) {
            int idx = t + rep * 256;
            int i = idx >> 6;
            int j = idx & 63;
            Xs[j][i] = X[(m0 + i) * EE + e0 + j];
            Ws[i][j] = W[(e0 + i) * AA + j];
        }
        __syncthreads();
#pragma unroll 8
        for (int e = 0; e < 64; e++) {
            float4 xa = *(const float4*)&Xs[e][ty * 4];
            float4 wb = *(const float4*)&Ws[e][tx * 4];
            acc[0][0] += xa.x * wb.x; acc[0][1] += xa.x * wb.y; acc[0][2] += xa.x * wb.z; acc[0][3] += xa.x * wb.w;
            acc[1][0] += xa.y * wb.x; acc[1][1] += xa.y * wb.y; acc[1][2] += xa.y * wb.z; acc[1][3] += xa.y * wb.w;
            acc[2][0] += xa.z * wb.x; acc[2][1] += xa.z * wb.y; acc[2][2] += xa.z * wb.z; acc[2][3] += xa.z * wb.w;
            acc[3][0] += xa.w * wb.x; acc[3][1] += xa.w * wb.y; acc[3][2] += xa.w * wb.z; acc[3][3] += xa.w * wb.w;
        }
        __syncthreads();
    }

#pragma unroll
    for (int r = 0; r < 4; r++) {
#pragma unroll
        for (int c = 0; c < 4; c++) {
            int n = tx * 4 + c;
            outp[(m0 + ty * 4 + r) * AA + n] = (acc[r][c] + bias[n]) * scl;
        }
    }
}

// ---------------------------------------------------------------------------
// Flash attention (causal), fp32 with f32x2 packed FMA.
// grid = (32, BB): CTA x handles q-tiles x and 63-x (perfect causal balance).
// block = 256 threads; BQ = BK = 64, D = 64.
// ---------------------------------------------------------------------------
__global__ __launch_bounds__(256, 2) void flash_kernel(float* __restrict__ out)
{
    extern __shared__ float sm[];
    float* Qt = sm;               // [64 d][68]  d-major: Qt[d][i]
    float* Kt = Qt + 64 * 68;     // [64 d][68]  d-major: Kt[d][j]
    float* Vs = Kt + 64 * 68;     // [64 j][68]  row-major: Vs[j][d]
    float* Pt = Vs + 64 * 68;     // [64 j][68]  TRANSPOSED probs: Pt[j][i]

    const int t  = threadIdx.x;
    const int tx = t & 15;
    const int ty = t >> 4;
    const int b  = blockIdx.y;

#pragma unroll 1
    for (int half = 0; half < 2; half++) {
        const int qt = (half == 0) ? blockIdx.x : 63 - blockIdx.x;

        const float* qp    = g_q + (b * TT + qt * 64) * AA;
        const float* kbase = g_k + b * TT * AA;
        const float* vbase = g_v + b * TT * AA;

        // load Q tile (transposed).  Covered by the first barrier in the loop.
#pragma unroll
        for (int rep = 0; rep < 16; rep++) {
            int idx = t + rep * 256;
            int i = idx >> 6;
            int a = idx & 63;
            Qt[a * 68 + i] = qp[i * AA + a];
        }

        float m_run[4], l_run[4];
        ull_t O2[4][2];
#pragma unroll
        for (int r = 0; r < 4; r++) {
            m_run[r] = -INFINITY; l_run[r] = 0.f;
            O2[r][0] = 0ULL; O2[r][1] = 0ULL;
        }

#pragma unroll 1
        for (int kt = 0; kt <= qt; kt++) {
            const float* kp = kbase + kt * 64 * AA;
            const float* vp = vbase + kt * 64 * AA;
#pragma unroll
            for (int rep = 0; rep < 16; rep++) {
                int idx = t + rep * 256;
                int i = idx >> 6;
                int a = idx & 63;
                Kt[a * 68 + i] = kp[i * AA + a];
                Vs[i * 68 + a] = vp[i * AA + a];
            }
            __syncthreads();   // A: K/V (and Q on first iter) visible

            // ---- S = Q @ K^T, packed f32x2 ----
            ull_t s2[4][2];
#pragma unroll
            for (int r = 0; r < 4; r++) { s2[r][0] = 0ULL; s2[r][1] = 0ULL; }

#pragma unroll 4
            for (int d = 0; d < 64; d++) {
                float4 qa = *(const float4*)&Qt[d * 68 + ty * 4];
                ulonglong2 kb = *(const ulonglong2*)&Kt[d * 68 + tx * 4];
                ull_t q0 = pack2(qa.x), q1 = pack2(qa.y), q2 = pack2(qa.z), q3 = pack2(qa.w);
                fma2(s2[0][0], q0, kb.x); fma2(s2[0][1], q0, kb.y);
                fma2(s2[1][0], q1, kb.x); fma2(s2[1][1], q1, kb.y);
                fma2(s2[2][0], q2, kb.x); fma2(s2[2][1], q2, kb.y);
                fma2(s2[3][0], q3, kb.x); fma2(s2[3][1], q3, kb.y);
            }

            float s[4][4];
#pragma unroll
            for (int r = 0; r < 4; r++) {
                unpack2(s2[r][0], s[r][0], s[r][1]);
                unpack2(s2[r][1], s[r][2], s[r][3]);
            }

            if (kt == qt) {
#pragma unroll
                for (int r = 0; r < 4; r++)
#pragma unroll
                    for (int c = 0; c < 4; c++)
                        if (tx * 4 + c > ty * 4 + r) s[r][c] = -INFINITY;
            }

            // ---- register softmax: reduce over the 16-lane tx group ----
            float rm[4];
#pragma unroll
            for (int r = 0; r < 4; r++)
                rm[r] = fmaxf(fmaxf(s[r][0], s[r][1]), fmaxf(s[r][2], s[r][3]));
#pragma unroll
            for (int off = 1; off < 16; off <<= 1) {
#pragma unroll
                for (int r = 0; r < 4; r++)
                    rm[r] = fmaxf(rm[r], __shfl_xor_sync(0xffffffffu, rm[r], off));
            }

            float corr[4];
#pragma unroll
            for (int r = 0; r < 4; r++) {
                float mnew = fmaxf(m_run[r], rm[r]);
                corr[r] = __expf(m_run[r] - mnew);   // m_run=-inf -> 0
                m_run[r] = mnew;
            }

            float rs[4];
#pragma unroll
            for (int r = 0; r < 4; r++) {
#pragma unroll
                for (int c = 0; c < 4; c++)
                    s[r][c] = __expf(s[r][c] - m_run[r]);
                rs[r] = (s[r][0] + s[r][1]) + (s[r][2] + s[r][3]);
            }
#pragma unroll
            for (int off = 1; off < 16; off <<= 1) {
#pragma unroll
                for (int r = 0; r < 4; r++)
                    rs[r] += __shfl_xor_sync(0xffffffffu, rs[r], off);
            }
#pragma unroll
            for (int r = 0; r < 4; r++)
                l_run[r] = l_run[r] * corr[r] + rs[r];

            // ---- write probs TRANSPOSED: Pt[col][row], float4 along rows ----
#pragma unroll
            for (int c = 0; c < 4; c++) {
                float4 pv = make_float4(s[0][c], s[1][c], s[2][c], s[3][c]);
                *(float4*)&Pt[(tx * 4 + c) * 68 + ty * 4] = pv;
            }
            __syncthreads();   // B: Pt visible

            // ---- O = O * corr + P @ V, packed f32x2 ----
#pragma unroll
            for (int r = 0; r < 4; r++) {
                ull_t cp = pack2(corr[r]);
                O2[r][0] = mul2(O2[r][0], cp);
                O2[r][1] = mul2(O2[r][1], cp);
            }

#pragma unroll 4
            for (int j = 0; j < 64; j++) {
                float4 pa = *(const float4*)&Pt[j * 68 + ty * 4];     // broadcast
                ulonglong2 vb = *(const ulonglong2*)&Vs[j * 68 + tx * 4];
                ull_t p0 = pack2(pa.x), p1 = pack2(pa.y), p2 = pack2(pa.z), p3 = pack2(pa.w);
                fma2(O2[0][0], p0, vb.x); fma2(O2[0][1], p0, vb.y);
                fma2(O2[1][0], p1, vb.x); fma2(O2[1][1], p1, vb.y);
                fma2(O2[2][0], p2, vb.x); fma2(O2[2][1], p2, vb.y);
                fma2(O2[3][0], p3, vb.x); fma2(O2[3][1], p3, vb.y);
            }
            __syncthreads();   // C: PV done, buffers free
        }

        // ---- epilogue ----
#pragma unroll
        for (int r = 0; r < 4; r++) {
            float inv = 1.0f / l_run[r];
            float o0, o1, o2, o3;
            unpack2(O2[r][0], o0, o1);
            unpack2(O2[r][1], o2, o3);
            float4 ov = make_float4(o0 * inv, o1 * inv, o2 * inv, o3 * inv);
            *(float4*)&out[(b * TT + qt * 64 + ty * 4 + r) * AA + tx * 4] = ov;
        }
        __syncthreads();   // Qt reuse safety for next half
    }
}

static const int FLASH_SMEM = 4 * 64 * 68 * (int)sizeof(float);  // 69632

extern "C" void kernel_launch(void* const* d_in, const int* in_sizes, int n_in,
                              void* d_out, int out_size)
{
    const float* X  = (const float*)d_in[0];
    const float* Wk = (const float*)d_in[1];
    const float* bk = (const float*)d_in[2];
    const float* Wq = (const float*)d_in[3];
    const float* bq = (const float*)d_in[4];
    const float* Wv = (const float*)d_in[5];
    const float* bv = (const float*)d_in[6];
    float* out = (float*)d_out;

    cudaFuncSetAttribute(flash_kernel, cudaFuncAttributeMaxDynamicSharedMemorySize, FLASH_SMEM);

    dim3 pg(MTOT / 64, 3);
    proj_kernel<<<pg, 256>>>(X, Wk, bk, Wq, bq, Wv, bv);

    dim3 fg(32, BB);
    flash_kernel<<<fg, 256, FLASH_SMEM>>>(out);
}